// round 10
// baseline (speedup 1.0000x reference)
#include <cuda_runtime.h>
#include <math.h>
#include <stdint.h>

// ---------------- problem constants ----------------
#define BB 8
#define NN 1024
#define DV 768
#define DS 512
#define FF 768
#define HH 12
#define DH 64
#define KG 1280        // Dv + Ds
#define ROWS (BB*NN)   // 8192
#define SCALE 0.125f   // dh^-0.5
#define EPS 1e-5f

// ---------------- scratch (device globals; no allocation allowed) ----------------
__device__ float g_gw[BB*HH*DV];      // scale * gv[d] * wqk[b,h,d]
__device__ float g_S1[BB*HH];         // sum_d gw
__device__ float g_S0[BB*HH];         // scale * sum_d bv[d]*wqk
__device__ float g_gsem[BB*DV];       // sem @ Wg[:,768:].T + bg
__device__ float g_mu[ROWS];
__device__ float g_rstd[ROWS];
__device__ float g_scores[BB*HH*NN];
__device__ float g_w[BB*HH*NN];       // attn * rstd
__device__ float g_t[BB*HH];          // sum_n attn*rstd*mu
#define NCHUNK 32
__device__ float g_vbarp[NCHUNK*BB*HH*DV];
__device__ float g_ctx[BB*FF];
__device__ float g_att[BB*DV];

// grid barrier state (self-resetting count; monotone sense — replay-safe)
__device__ unsigned g_count = 0;
__device__ volatile unsigned g_sense = 0;

// ---------------- generic helpers ----------------
__device__ __forceinline__ float warp_sum(float v) {
#pragma unroll
    for (int o = 16; o > 0; o >>= 1) v += __shfl_down_sync(0xffffffffu, v, o);
    return v;
}
__device__ __forceinline__ float warp_sum_all(float v) {
#pragma unroll
    for (int o = 16; o > 0; o >>= 1) v += __shfl_xor_sync(0xffffffffu, v, o);
    return v;
}
__device__ __forceinline__ float warp_max(float v) {
#pragma unroll
    for (int o = 16; o > 0; o >>= 1) v = fmaxf(v, __shfl_down_sync(0xffffffffu, v, o));
    return v;
}
__device__ __forceinline__ float block_sum256(float v, float* red) {
    int lane = threadIdx.x & 31, wid = threadIdx.x >> 5;
    __syncthreads();
    v = warp_sum(v);
    if (lane == 0) red[wid] = v;
    __syncthreads();
    if (wid == 0) {
        float x = (lane < 8) ? red[lane] : 0.f;
        x = warp_sum(x);
        if (lane == 0) red[0] = x;
    }
    __syncthreads();
    return red[0];
}
__device__ __forceinline__ float block_max256(float v, float* red) {
    int lane = threadIdx.x & 31, wid = threadIdx.x >> 5;
    __syncthreads();
    v = warp_max(v);
    if (lane == 0) red[wid] = v;
    __syncthreads();
    if (wid == 0) {
        float x = (lane < 8) ? red[lane] : -1e30f;
        x = warp_max(x);
        if (lane == 0) red[0] = x;
    }
    __syncthreads();
    return red[0];
}

#define CP16(dst, src)   asm volatile("cp.async.cg.shared.global [%0], [%1], 16;" :: "r"(dst), "l"(src) : "memory")
#define CP_COMMIT()      asm volatile("cp.async.commit_group;" ::: "memory")

__device__ __forceinline__ uint32_t smem_u32(const void* p) {
    uint32_t a;
    asm("{ .reg .u64 t; cvta.to.shared.u64 t, %1; cvt.u32.u64 %0, t; }" : "=r"(a) : "l"(p));
    return a;
}

// m16n8k8 tf32 mma (row.col), D = A*B + D. Operands hold raw fp32 bits.
__device__ __forceinline__ void mma_tf32(float* c, const uint32_t* a, const uint32_t* b) {
    asm volatile(
        "mma.sync.aligned.m16n8k8.row.col.f32.tf32.tf32.f32 "
        "{%0,%1,%2,%3}, {%4,%5,%6,%7}, {%8,%9}, {%0,%1,%2,%3};"
        : "+f"(c[0]), "+f"(c[1]), "+f"(c[2]), "+f"(c[3])
        : "r"(a[0]), "r"(a[1]), "r"(a[2]), "r"(a[3]), "r"(b[0]), "r"(b[1]));
}

// grid-wide barrier v2: arrival via one atomicAdd per block; waiting via plain
// volatile LOADS of the sense word (L2 same-line reads broadcast — no atomic
// serialization) with nanosleep backoff. Sense read BEFORE arrival -> safe.
__device__ __forceinline__ void gbar() {
    __threadfence();
    __syncthreads();
    if (threadIdx.x == 0) {
        unsigned s = g_sense;                      // volatile read, pre-arrival
        unsigned old = atomicAdd(&g_count, 1u);
        if (old == gridDim.x - 1) {
            atomicExch(&g_count, 0u);
            __threadfence();
            atomicAdd((unsigned*)&g_sense, 1u);
        } else {
            while (g_sense == s) __nanosleep(128); // volatile load poll
        }
        __threadfence();
    }
    __syncthreads();
}

// ---------------- K5 tile constants ----------------
#define K5_LDA 36
#define K5_TILE_BYTES (128*K5_LDA*4)       // 18432
#define K5_A_OFF(s) ((s)*2*K5_TILE_BYTES)
#define K5_B_OFF(s) ((s)*2*K5_TILE_BYTES + K5_TILE_BYTES)
#define MEGA_SMEM (4*K5_TILE_BYTES)        // 73728; aliased by gw_s / C staging
#define K5_CS 132

// ================= persistent megakernel =================
__global__ void __launch_bounds__(256, 2)
mega(const float* __restrict__ vis, const float* __restrict__ sem,
     const float* __restrict__ Wq, const float* __restrict__ Wk,
     const float* __restrict__ Wv, const float* __restrict__ Wo,
     const float* __restrict__ bo, const float* __restrict__ Wg,
     const float* __restrict__ bg, const float* __restrict__ gv,
     const float* __restrict__ bv, const float* __restrict__ gs,
     const float* __restrict__ bs, float* __restrict__ out)
{
    extern __shared__ float smem[];
    __shared__ float sm[DS];
    __shared__ float red[8];
    __shared__ float qh[DH];
    __shared__ float s1s[HH], s0s[HH];
    __shared__ float ws[HH][32];
    __shared__ float u[DV];
    int tid = threadIdx.x, lane = tid & 31, wid = tid >> 5;
    int G = gridDim.x;

    // ---------- P0: semantic LN + q_h -> gw/S1/S0 ; gsem ----------
    for (int blk = blockIdx.x; blk < 104; blk += G) {
        if (blk < 96) {
            int b = blk / 12, h = blk % 12;
            float sum = 0.f, sq = 0.f;
            for (int i = tid; i < DS; i += 256) {
                float v = sem[b*DS + i];
                sm[i] = v; sum += v; sq += v*v;
            }
            sum = block_sum256(sum, red);
            sq  = block_sum256(sq, red);
            float mu = sum * (1.f/DS);
            float rstd = rsqrtf(sq * (1.f/DS) - mu*mu + EPS);
            for (int i = tid; i < DS; i += 256)
                sm[i] = (sm[i] - mu) * rstd * gs[i] + bs[i];
            __syncthreads();
            for (int j = wid; j < DH; j += 8) {
                int f = h*DH + j;
                float dot = 0.f;
                for (int s = lane; s < DS; s += 32) dot += sm[s] * Wq[(size_t)f*DS + s];
                dot = warp_sum(dot);
                if (lane == 0) qh[j] = dot;
            }
            __syncthreads();
            float s1p = 0.f, s0p = 0.f;
            for (int d = tid; d < DV; d += 256) {
                float s = 0.f;
#pragma unroll 16
                for (int j = 0; j < DH; j++) s += qh[j] * Wk[(size_t)(h*DH + j)*DV + d];
                s *= SCALE;
                float gwv = gv[d] * s;
                g_gw[(b*HH + h)*DV + d] = gwv;
                s1p += gwv;
                s0p += bv[d] * s;
            }
            s1p = block_sum256(s1p, red);
            s0p = block_sum256(s0p, red);
            if (tid == 0) { g_S1[b*HH + h] = s1p; g_S0[b*HH + h] = s0p; }
            __syncthreads();
        } else {
            int b = blk - 96;
            for (int i = tid; i < DS; i += 256) sm[i] = sem[b*DS + i];
            __syncthreads();
            for (int dv = wid; dv < DV; dv += 8) {
                float dot = 0.f;
                for (int s = lane; s < DS; s += 32) dot += sm[s] * Wg[(size_t)dv*KG + DV + s];
                dot = warp_sum(dot);
                if (lane == 0) g_gsem[b*DV + dv] = dot + bg[dv];
            }
            __syncthreads();
        }
    }
    gbar();

    // ---------- P1: visual LN stats + scores (32 rows/task) ----------
    for (int task = blockIdx.x; task < ROWS/32; task += G) {
        float* gw_s = smem;      // 36 KB alias
        int row0 = task * 32;
        int b = row0 >> 10;
        {
            const float4* gsrc = (const float4*)(g_gw + b*HH*DV);
            float4* gdst = (float4*)gw_s;
#pragma unroll
            for (int i = 0; i < 9; i++) gdst[tid + i*256] = gsrc[tid + i*256];
        }
        if (tid < HH) { s1s[tid] = g_S1[b*HH + tid]; s0s[tid] = g_S0[b*HH + tid]; }
        __syncthreads();
#pragma unroll
        for (int rr = 0; rr < 4; rr++) {
            int row = row0 + wid*4 + rr;
            const float4* x4 = (const float4*)(vis + (size_t)row * DV);
            float4 xv[6];
#pragma unroll
            for (int s = 0; s < 6; s++) xv[s] = x4[s*32 + lane];
            float sum = 0.f, sq = 0.f;
#pragma unroll
            for (int s = 0; s < 6; s++) {
                sum += xv[s].x + xv[s].y + xv[s].z + xv[s].w;
                sq  += xv[s].x*xv[s].x + xv[s].y*xv[s].y + xv[s].z*xv[s].z + xv[s].w*xv[s].w;
            }
            sum = warp_sum_all(sum);
            sq  = warp_sum_all(sq);
            float mu = sum * (1.f/DV);
            float rstd = rsqrtf(sq * (1.f/DV) - mu*mu + EPS);
            if (lane == 0) { g_mu[row] = mu; g_rstd[row] = rstd; }
            int n = row & (NN - 1);
#pragma unroll 2
            for (int h = 0; h < HH; h++) {
                const float4* g4 = (const float4*)(gw_s + h*DV);
                float dot = 0.f;
#pragma unroll
                for (int s = 0; s < 6; s++) {
                    float4 gv4 = g4[s*32 + lane];
                    dot += xv[s].x*gv4.x + xv[s].y*gv4.y + xv[s].z*gv4.z + xv[s].w*gv4.w;
                }
                dot = warp_sum(dot);
                if (lane == 0)
                    g_scores[(b*HH + h)*NN + n] = rstd * (dot - mu*s1s[h]) + s0s[h];
            }
        }
        __syncthreads();
    }
    gbar();

    // ---------- P2: softmax; w = attn*rstd, t ----------
    for (int bh = blockIdx.x; bh < BB*HH; bh += G) {
        int b = bh / HH;
        float loc[4];
        float mx = -1e30f;
#pragma unroll
        for (int i = 0; i < 4; i++) {
            loc[i] = g_scores[bh*NN + tid + i*256];
            mx = fmaxf(mx, loc[i]);
        }
        mx = block_max256(mx, red);
        float s = 0.f;
#pragma unroll
        for (int i = 0; i < 4; i++) { loc[i] = expf(loc[i] - mx); s += loc[i]; }
        s = block_sum256(s, red);
        float inv = 1.f / s;
        float tp = 0.f;
#pragma unroll
        for (int i = 0; i < 4; i++) {
            int n = tid + i*256;
            float a = loc[i] * inv;
            float rs = g_rstd[b*NN + n];
            float w = a * rs;
            g_w[bh*NN + n] = w;
            tp += w * g_mu[b*NN + n];
        }
        tp = block_sum256(tp, red);
        if (tid == 0) g_t[bh] = tp;
        __syncthreads();
    }
    gbar();

    // ---------- P3: per-chunk partial vbar (256 threads, 3 slices) ----------
    for (int task = blockIdx.x; task < NCHUNK*BB; task += G) {
        int chunk = task & (NCHUNK - 1);
        int b = task >> 5;
        int n0 = chunk * 32;
        for (int i = tid; i < HH*32; i += 256) {
            ws[i >> 5][i & 31] = g_w[(b*HH + (i >> 5))*NN + n0 + (i & 31)];
        }
        __syncthreads();
#pragma unroll
        for (int sl = 0; sl < 3; sl++) {
            int d = sl*256 + tid;
            float acc[HH];
#pragma unroll
            for (int h = 0; h < HH; h++) acc[h] = 0.f;
            const float* base = vis + ((size_t)(b << 10) + n0) * DV + d;
#pragma unroll 4
            for (int j = 0; j < 32; j++) {
                float x = base[(size_t)j * DV];
#pragma unroll
                for (int h = 0; h < HH; h++) acc[h] += ws[h][j] * x;
            }
#pragma unroll
            for (int h = 0; h < HH; h++)
                g_vbarp[(size_t)chunk*(BB*HH*DV) + (b*HH + h)*DV + d] = acc[h];
        }
        __syncthreads();
    }
    gbar();

    // ---------- P4: chunk-reduce + u + ctx ----------
    for (int task = blockIdx.x; task < BB*HH; task += G) {
        int h = task % HH, b = task / HH;
        float t = g_t[b*HH + h];
        int base = (b*HH + h)*DV;
        for (int d = tid; d < DV; d += 256) {
            float s = 0.f;
#pragma unroll
            for (int c = 0; c < NCHUNK; c++) s += g_vbarp[(size_t)c*(BB*HH*DV) + base + d];
            u[d] = gv[d] * (s - t) + bv[d];
        }
        __syncthreads();
        for (int j = wid; j < DH; j += 8) {
            int f = h*DH + j;
            float dot = 0.f;
            for (int d = lane; d < DV; d += 32) dot += u[d] * Wv[(size_t)f*DV + d];
            dot = warp_sum(dot);
            if (lane == 0) g_ctx[b*FF + f] = dot;
        }
        __syncthreads();
    }
    gbar();

    // ---------- P5: attended = ctx @ Wo.T + bo ----------
    for (int b = blockIdx.x; b < BB; b += G) {
        for (int i = tid; i < FF; i += 256) u[i] = g_ctx[b*FF + i];
        __syncthreads();
        for (int dv = wid; dv < DV; dv += 8) {
            float dot = 0.f;
            for (int f = lane; f < FF; f += 32) dot += u[f] * Wo[(size_t)dv*FF + f];
            dot = warp_sum(dot);
            if (lane == 0) g_att[b*DV + dv] = dot + bo[dv];
        }
        __syncthreads();
    }
    gbar();

    // ---------- P6: gate GEMM (tf32 mma) + fused epilogue ----------
    for (int task = blockIdx.x; task < 384; task += G) {
        uint32_t sbase = smem_u32(smem);
        int rowBase = (task & 63) * 128;
        int colBase = (task >> 6) * 128;
        int warp_m = wid >> 2;
        int warp_n = wid & 3;
        int g = lane >> 2, tig = lane & 3;

        uint32_t dsto[4];
        const float* srcA[4];
        const float* srcB[4];
#pragma unroll
        for (int i = 0; i < 4; i++) {
            int idx = tid + i*256;
            int row = idx >> 3, seg = idx & 7;
            dsto[i] = (uint32_t)((row*K5_LDA + seg*4) * 4);
            srcA[i] = vis + (size_t)(rowBase + row)*DV + seg*4;
            srcB[i] = Wg  + (size_t)(colBase + row)*KG + seg*4;
        }

        float cf[4][4][4];
#pragma unroll
        for (int mi = 0; mi < 4; mi++)
#pragma unroll
            for (int ni = 0; ni < 4; ni++)
#pragma unroll
                for (int e = 0; e < 4; e++) cf[mi][ni][e] = 0.f;

#pragma unroll
        for (int i = 0; i < 4; i++) {
            CP16(sbase + K5_A_OFF(0) + dsto[i], srcA[i]);
            CP16(sbase + K5_B_OFF(0) + dsto[i], srcB[i]);
        }
        CP_COMMIT();

        int buf = 0;
        for (int kt = 0; kt < 24; kt++) {
            if (kt + 1 < 24) {
#pragma unroll
                for (int i = 0; i < 4; i++) {
                    CP16(sbase + K5_A_OFF(buf^1) + dsto[i], srcA[i] + (kt+1)*32);
                    CP16(sbase + K5_B_OFF(buf^1) + dsto[i], srcB[i] + (kt+1)*32);
                }
                CP_COMMIT();
                asm volatile("cp.async.wait_group 1;" ::: "memory");
            } else {
                asm volatile("cp.async.wait_group 0;" ::: "memory");
            }
            __syncthreads();

            const float* As = smem + (K5_A_OFF(buf) >> 2);
            const float* Bs = smem + (K5_B_OFF(buf) >> 2);
#pragma unroll
            for (int ks = 0; ks < 4; ks++) {
                int k0 = ks*8;
                uint32_t af[4][4], bfr[4][2];
#pragma unroll
                for (int mi = 0; mi < 4; mi++) {
                    int r0 = warp_m*64 + mi*16 + g;
                    af[mi][0] = __float_as_uint(As[r0*K5_LDA + k0 + tig]);
                    af[mi][1] = __float_as_uint(As[(r0+8)*K5_LDA + k0 + tig]);
                    af[mi][2] = __float_as_uint(As[r0*K5_LDA + k0 + tig + 4]);
                    af[mi][3] = __float_as_uint(As[(r0+8)*K5_LDA + k0 + tig + 4]);
                }
#pragma unroll
                for (int ni = 0; ni < 4; ni++) {
                    int c0 = warp_n*32 + ni*8 + g;
                    bfr[ni][0] = __float_as_uint(Bs[c0*K5_LDA + k0 + tig]);
                    bfr[ni][1] = __float_as_uint(Bs[c0*K5_LDA + k0 + tig + 4]);
                }
#pragma unroll
                for (int mi = 0; mi < 4; mi++)
#pragma unroll
                    for (int ni = 0; ni < 4; ni++)
                        mma_tf32(cf[mi][ni], af[mi], bfr[ni]);
            }
            __syncthreads();
            buf ^= 1;
        }

        // stage accumulators into smem
#pragma unroll
        for (int mi = 0; mi < 4; mi++) {
            int r0 = warp_m*64 + mi*16 + g;
#pragma unroll
            for (int ni = 0; ni < 4; ni++) {
                int c0 = warp_n*32 + ni*8 + 2*tig;
                smem[r0*K5_CS + c0]         = cf[mi][ni][0];
                smem[r0*K5_CS + c0 + 1]     = cf[mi][ni][1];
                smem[(r0+8)*K5_CS + c0]     = cf[mi][ni][2];
                smem[(r0+8)*K5_CS + c0 + 1] = cf[mi][ni][3];
            }
        }
        __syncthreads();

        int b = rowBase >> 10;
        const float* gsp = g_gsem + b*DV;
        const float* at = g_att + b*DV;
#pragma unroll
        for (int j = 0; j < 16; j++) {
            int idx = tid + j*256;
            int row = idx >> 5, c4 = idx & 31;
            int r = rowBase + row;
            int c = colBase + c4*4;
            const float* Cr = smem + row*K5_CS + c4*4;
            float4 av = *(const float4*)(vis + (size_t)r*DV + c);
            float4 o;
            o.x = av.x + at[c+0] * (1.f/(1.f + __expf(-(Cr[0] + gsp[c+0]))));
            o.y = av.y + at[c+1] * (1.f/(1.f + __expf(-(Cr[1] + gsp[c+1]))));
            o.z = av.z + at[c+2] * (1.f/(1.f + __expf(-(Cr[2] + gsp[c+2]))));
            o.w = av.w + at[c+3] * (1.f/(1.f + __expf(-(Cr[3] + gsp[c+3]))));
            *(float4*)(out + (size_t)r*DV + c) = o;
        }
        __syncthreads();    // smem reused if this block takes another tile
    }
}

// ---------------- launcher (single graph node) ----------------
extern "C" void kernel_launch(void* const* d_in, const int* in_sizes, int n_in,
                              void* d_out, int out_size) {
    const float* visual   = (const float*)d_in[0];
    const float* semantic = (const float*)d_in[1];
    const float* Wq = (const float*)d_in[2];
    const float* Wk = (const float*)d_in[3];
    const float* Wv = (const float*)d_in[4];
    const float* Wo = (const float*)d_in[5];
    const float* bo = (const float*)d_in[6];
    const float* Wg = (const float*)d_in[7];
    const float* bg = (const float*)d_in[8];
    const float* gv = (const float*)d_in[9];
    const float* bv = (const float*)d_in[10];
    const float* gs = (const float*)d_in[11];
    const float* bs = (const float*)d_in[12];
    float* out = (float*)d_out;

    cudaFuncSetAttribute(mega, cudaFuncAttributeMaxDynamicSharedMemorySize, MEGA_SMEM);

    int dev = 0;
    cudaGetDevice(&dev);
    int nsm = 148;
    cudaDeviceGetAttribute(&nsm, cudaDevAttrMultiProcessorCount, dev);
    int occ = 0;
    cudaOccupancyMaxActiveBlocksPerMultiprocessor(&occ, mega, 256, MEGA_SMEM);
    if (occ < 1) occ = 1;
    int G = nsm * occ;

    mega<<<G, 256, MEGA_SMEM>>>(visual, semantic, Wq, Wk, Wv, Wo, bo,
                                Wg, bg, gv, bv, gs, bs, out);
}

// round 11
// speedup vs baseline: 1.3950x; 1.3950x over previous
#include <cuda_runtime.h>
#include <math.h>
#include <stdint.h>

// ---------------- problem constants ----------------
#define BB 8
#define NN 1024
#define DV 768
#define DS 512
#define FF 768
#define HH 12
#define DH 64
#define KG 1280        // Dv + Ds
#define ROWS (BB*NN)   // 8192
#define SCALE 0.125f   // dh^-0.5
#define EPS 1e-5f

// ---------------- scratch (device globals; no allocation allowed) ----------------
__device__ float g_gw[BB*HH*DV];
__device__ float g_S1[BB*HH];
__device__ float g_S0[BB*HH];
__device__ float g_gsem[BB*DV];
__device__ float g_mu[ROWS];
__device__ float g_rstd[ROWS];
__device__ float g_scores[BB*HH*NN];
__device__ float g_w[BB*HH*NN];
__device__ float g_t[BB*HH];
#define NCHUNK 16
__device__ float g_vbarp[NCHUNK*BB*HH*DV];
__device__ float g_ctx[BB*FF];
__device__ float g_att[BB*DV];
__device__ float g_logits[ROWS*DV];     // raw gate logits from group-B GEMM

// barriers: group-A chain + full-grid join
__device__ unsigned g_cntA = 0;
__device__ volatile unsigned g_senseA = 0;
__device__ unsigned g_cntJ = 0;
__device__ volatile unsigned g_senseJ = 0;

// ---------------- generic helpers ----------------
__device__ __forceinline__ float warp_sum(float v) {
#pragma unroll
    for (int o = 16; o > 0; o >>= 1) v += __shfl_down_sync(0xffffffffu, v, o);
    return v;
}
__device__ __forceinline__ float warp_sum_all(float v) {
#pragma unroll
    for (int o = 16; o > 0; o >>= 1) v += __shfl_xor_sync(0xffffffffu, v, o);
    return v;
}
__device__ __forceinline__ float warp_max(float v) {
#pragma unroll
    for (int o = 16; o > 0; o >>= 1) v = fmaxf(v, __shfl_down_sync(0xffffffffu, v, o));
    return v;
}
__device__ __forceinline__ float block_sum256(float v, float* red) {
    int lane = threadIdx.x & 31, wid = threadIdx.x >> 5;
    __syncthreads();
    v = warp_sum(v);
    if (lane == 0) red[wid] = v;
    __syncthreads();
    if (wid == 0) {
        float x = (lane < 8) ? red[lane] : 0.f;
        x = warp_sum(x);
        if (lane == 0) red[0] = x;
    }
    __syncthreads();
    return red[0];
}
__device__ __forceinline__ float block_max256(float v, float* red) {
    int lane = threadIdx.x & 31, wid = threadIdx.x >> 5;
    __syncthreads();
    v = warp_max(v);
    if (lane == 0) red[wid] = v;
    __syncthreads();
    if (wid == 0) {
        float x = (lane < 8) ? red[lane] : -1e30f;
        x = warp_max(x);
        if (lane == 0) red[0] = x;
    }
    __syncthreads();
    return red[0];
}

#define CP16(dst, src)   asm volatile("cp.async.cg.shared.global [%0], [%1], 16;" :: "r"(dst), "l"(src) : "memory")
#define CP_COMMIT()      asm volatile("cp.async.commit_group;" ::: "memory")

__device__ __forceinline__ uint32_t smem_u32(const void* p) {
    uint32_t a;
    asm("{ .reg .u64 t; cvta.to.shared.u64 t, %1; cvt.u32.u64 %0, t; }" : "=r"(a) : "l"(p));
    return a;
}

__device__ __forceinline__ void mma_tf32(float* c, const uint32_t* a, const uint32_t* b) {
    asm volatile(
        "mma.sync.aligned.m16n8k8.row.col.f32.tf32.tf32.f32 "
        "{%0,%1,%2,%3}, {%4,%5,%6,%7}, {%8,%9}, {%0,%1,%2,%3};"
        : "+f"(c[0]), "+f"(c[1]), "+f"(c[2]), "+f"(c[3])
        : "r"(a[0]), "r"(a[1]), "r"(a[2]), "r"(a[3]), "r"(b[0]), "r"(b[1]));
}

// group barrier: arrival via atomic; wait via volatile load + nanosleep.
__device__ __forceinline__ void gbarX(unsigned* cnt, volatile unsigned* sense, unsigned target) {
    __threadfence();
    __syncthreads();
    if (threadIdx.x == 0) {
        unsigned s = *sense;
        unsigned old = atomicAdd(cnt, 1u);
        if (old == target - 1) {
            atomicExch(cnt, 0u);
            __threadfence();
            atomicAdd((unsigned*)sense, 1u);
        } else {
            while (*sense == s) __nanosleep(128);
        }
        __threadfence();
    }
    __syncthreads();
}

// ---------------- K5 tile constants ----------------
#define K5_LDA 36
#define K5_TILE_BYTES (128*K5_LDA*4)       // 18432
#define K5_A_OFF(s) ((s)*2*K5_TILE_BYTES)
#define K5_B_OFF(s) ((s)*2*K5_TILE_BYTES + K5_TILE_BYTES)
#define MEGA_SMEM (4*K5_TILE_BYTES)        // 73728
#define K5_CS 132

// ================= persistent dual-pipeline megakernel =================
__global__ void __launch_bounds__(256, 2)
mega(const float* __restrict__ vis, const float* __restrict__ sem,
     const float* __restrict__ Wq, const float* __restrict__ Wk,
     const float* __restrict__ Wv, const float* __restrict__ Wo,
     const float* __restrict__ bo, const float* __restrict__ Wg,
     const float* __restrict__ bg, const float* __restrict__ gv,
     const float* __restrict__ bv, const float* __restrict__ gs,
     const float* __restrict__ bs, float* __restrict__ out)
{
    extern __shared__ float smem[];
    __shared__ float sm[DS];
    __shared__ float red[8];
    __shared__ float qh[DH];
    __shared__ float s1s[HH], s0s[HH];
    __shared__ float ws[HH][64];
    __shared__ float u[DV];
    int tid = threadIdx.x, lane = tid & 31, wid = tid >> 5;
    int G = gridDim.x;
    unsigned GA = (unsigned)(G >> 1);              // attention group size
    unsigned GB = (unsigned)G - GA;                // gemm group size
    int bid = blockIdx.x;
    bool isA = (unsigned)bid < GA;

    if (isA) {
        int rk = bid;
        // ---------- P0: semantic LN + q_h -> gw/S1/S0 ; gsem ----------
        for (int blk = rk; blk < 104; blk += GA) {
            if (blk < 96) {
                int b = blk / 12, h = blk % 12;
                float sum = 0.f, sq = 0.f;
                for (int i = tid; i < DS; i += 256) {
                    float v = sem[b*DS + i];
                    sm[i] = v; sum += v; sq += v*v;
                }
                sum = block_sum256(sum, red);
                sq  = block_sum256(sq, red);
                float mu = sum * (1.f/DS);
                float rstd = rsqrtf(sq * (1.f/DS) - mu*mu + EPS);
                for (int i = tid; i < DS; i += 256)
                    sm[i] = (sm[i] - mu) * rstd * gs[i] + bs[i];
                __syncthreads();
                for (int j = wid; j < DH; j += 8) {
                    int f = h*DH + j;
                    float dot = 0.f;
                    for (int s = lane; s < DS; s += 32) dot += sm[s] * Wq[(size_t)f*DS + s];
                    dot = warp_sum(dot);
                    if (lane == 0) qh[j] = dot;
                }
                __syncthreads();
                float s1p = 0.f, s0p = 0.f;
                for (int d = tid; d < DV; d += 256) {
                    float s = 0.f;
#pragma unroll 16
                    for (int j = 0; j < DH; j++) s += qh[j] * Wk[(size_t)(h*DH + j)*DV + d];
                    s *= SCALE;
                    float gwv = gv[d] * s;
                    g_gw[(b*HH + h)*DV + d] = gwv;
                    s1p += gwv;
                    s0p += bv[d] * s;
                }
                s1p = block_sum256(s1p, red);
                s0p = block_sum256(s0p, red);
                if (tid == 0) { g_S1[b*HH + h] = s1p; g_S0[b*HH + h] = s0p; }
                __syncthreads();
            } else {
                int b = blk - 96;
                for (int i = tid; i < DS; i += 256) sm[i] = sem[b*DS + i];
                __syncthreads();
                for (int dv = wid; dv < DV; dv += 8) {
                    float dot = 0.f;
                    for (int s = lane; s < DS; s += 32) dot += sm[s] * Wg[(size_t)dv*KG + DV + s];
                    dot = warp_sum(dot);
                    if (lane == 0) g_gsem[b*DV + dv] = dot + bg[dv];
                }
                __syncthreads();
            }
        }
        gbarX(&g_cntA, &g_senseA, GA);

        // ---------- P1: visual LN stats + scores (64 rows/task, 128 tasks) ----------
        for (int task = rk; task < ROWS/64; task += GA) {
            float* gw_s = smem;      // 36 KB alias
            int row0 = task * 64;
            int b = row0 >> 10;
            {
                const float4* gsrc = (const float4*)(g_gw + b*HH*DV);
                float4* gdst = (float4*)gw_s;
#pragma unroll
                for (int i = 0; i < 9; i++) gdst[tid + i*256] = gsrc[tid + i*256];
            }
            if (tid < HH) { s1s[tid] = g_S1[b*HH + tid]; s0s[tid] = g_S0[b*HH + tid]; }
            __syncthreads();
#pragma unroll
            for (int rr = 0; rr < 8; rr++) {
                int row = row0 + wid*8 + rr;
                const float4* x4 = (const float4*)(vis + (size_t)row * DV);
                float4 xv[6];
#pragma unroll
                for (int s = 0; s < 6; s++) xv[s] = x4[s*32 + lane];
                float sum = 0.f, sq = 0.f;
#pragma unroll
                for (int s = 0; s < 6; s++) {
                    sum += xv[s].x + xv[s].y + xv[s].z + xv[s].w;
                    sq  += xv[s].x*xv[s].x + xv[s].y*xv[s].y + xv[s].z*xv[s].z + xv[s].w*xv[s].w;
                }
                sum = warp_sum_all(sum);
                sq  = warp_sum_all(sq);
                float mu = sum * (1.f/DV);
                float rstd = rsqrtf(sq * (1.f/DV) - mu*mu + EPS);
                if (lane == 0) { g_mu[row] = mu; g_rstd[row] = rstd; }
                int n = row & (NN - 1);
#pragma unroll 2
                for (int h = 0; h < HH; h++) {
                    const float4* g4 = (const float4*)(gw_s + h*DV);
                    float dot = 0.f;
#pragma unroll
                    for (int s = 0; s < 6; s++) {
                        float4 gv4 = g4[s*32 + lane];
                        dot += xv[s].x*gv4.x + xv[s].y*gv4.y + xv[s].z*gv4.z + xv[s].w*gv4.w;
                    }
                    dot = warp_sum(dot);
                    if (lane == 0)
                        g_scores[(b*HH + h)*NN + n] = rstd * (dot - mu*s1s[h]) + s0s[h];
                }
            }
            __syncthreads();
        }
        gbarX(&g_cntA, &g_senseA, GA);

        // ---------- P2: softmax; w = attn*rstd, t ----------
        for (int bh = rk; bh < BB*HH; bh += GA) {
            int b = bh / HH;
            float loc[4];
            float mx = -1e30f;
#pragma unroll
            for (int i = 0; i < 4; i++) {
                loc[i] = g_scores[bh*NN + tid + i*256];
                mx = fmaxf(mx, loc[i]);
            }
            mx = block_max256(mx, red);
            float s = 0.f;
#pragma unroll
            for (int i = 0; i < 4; i++) { loc[i] = expf(loc[i] - mx); s += loc[i]; }
            s = block_sum256(s, red);
            float inv = 1.f / s;
            float tp = 0.f;
#pragma unroll
            for (int i = 0; i < 4; i++) {
                int n = tid + i*256;
                float a = loc[i] * inv;
                float rs = g_rstd[b*NN + n];
                float w = a * rs;
                g_w[bh*NN + n] = w;
                tp += w * g_mu[b*NN + n];
            }
            tp = block_sum256(tp, red);
            if (tid == 0) g_t[bh] = tp;
            __syncthreads();
        }
        gbarX(&g_cntA, &g_senseA, GA);

        // ---------- P3: per-chunk partial vbar (16 chunks of 64 tokens) ----------
        for (int task = rk; task < NCHUNK*BB; task += GA) {
            int chunk = task & (NCHUNK - 1);
            int b = task >> 4;
            int n0 = chunk * 64;
            for (int i = tid; i < HH*64; i += 256)
                ws[i >> 6][i & 63] = g_w[(b*HH + (i >> 6))*NN + n0 + (i & 63)];
            __syncthreads();
#pragma unroll
            for (int sl = 0; sl < 3; sl++) {
                int d = sl*256 + tid;
                float acc[HH];
#pragma unroll
                for (int h = 0; h < HH; h++) acc[h] = 0.f;
                const float* base = vis + ((size_t)(b << 10) + n0) * DV + d;
#pragma unroll 4
                for (int j = 0; j < 64; j++) {
                    float x = base[(size_t)j * DV];
#pragma unroll
                    for (int h = 0; h < HH; h++) acc[h] += ws[h][j] * x;
                }
#pragma unroll
                for (int h = 0; h < HH; h++)
                    g_vbarp[(size_t)chunk*(BB*HH*DV) + (b*HH + h)*DV + d] = acc[h];
            }
            __syncthreads();
        }
        gbarX(&g_cntA, &g_senseA, GA);

        // ---------- P4: chunk-reduce + u + ctx ----------
        for (int task = rk; task < BB*HH; task += GA) {
            int h = task % HH, b = task / HH;
            float t = g_t[b*HH + h];
            int base = (b*HH + h)*DV;
            for (int d = tid; d < DV; d += 256) {
                float s = 0.f;
#pragma unroll
                for (int c = 0; c < NCHUNK; c++) s += g_vbarp[(size_t)c*(BB*HH*DV) + base + d];
                u[d] = gv[d] * (s - t) + bv[d];
            }
            __syncthreads();
            for (int j = wid; j < DH; j += 8) {
                int f = h*DH + j;
                float dot = 0.f;
                for (int d = lane; d < DV; d += 32) dot += u[d] * Wv[(size_t)f*DV + d];
                dot = warp_sum(dot);
                if (lane == 0) g_ctx[b*FF + f] = dot;
            }
            __syncthreads();
        }
        gbarX(&g_cntA, &g_senseA, GA);

        // ---------- P5: attended = ctx @ Wo.T + bo  (128 tasks: b x 16 col-groups) ----------
        for (int task = rk; task < 128; task += GA) {
            int b = task >> 4, cg = task & 15;     // 48 cols per group
            for (int i = tid; i < FF; i += 256) u[i] = g_ctx[b*FF + i];
            __syncthreads();
            for (int j = wid; j < 48; j += 8) {
                int dv = cg*48 + j;
                float dot = 0.f;
                for (int f = lane; f < FF; f += 32) dot += u[f] * Wo[(size_t)dv*FF + f];
                dot = warp_sum(dot);
                if (lane == 0) g_att[b*DV + dv] = dot + bo[dv];
            }
            __syncthreads();
        }
    } else {
        // ================= group B: gate GEMM mainloop -> g_logits =================
        int rkB = bid - (int)GA;
        for (int task = rkB; task < 384; task += (int)GB) {
            uint32_t sbase = smem_u32(smem);
            int rowBase = (task & 63) * 128;
            int colBase = (task >> 6) * 128;
            int warp_m = wid >> 2;
            int warp_n = wid & 3;
            int g = lane >> 2, tig = lane & 3;

            uint32_t dsto[4];
            const float* srcA[4];
            const float* srcB[4];
#pragma unroll
            for (int i = 0; i < 4; i++) {
                int idx = tid + i*256;
                int row = idx >> 3, seg = idx & 7;
                dsto[i] = (uint32_t)((row*K5_LDA + seg*4) * 4);
                srcA[i] = vis + (size_t)(rowBase + row)*DV + seg*4;
                srcB[i] = Wg  + (size_t)(colBase + row)*KG + seg*4;
            }

            float cf[4][4][4];
#pragma unroll
            for (int mi = 0; mi < 4; mi++)
#pragma unroll
                for (int ni = 0; ni < 4; ni++)
#pragma unroll
                    for (int e = 0; e < 4; e++) cf[mi][ni][e] = 0.f;

#pragma unroll
            for (int i = 0; i < 4; i++) {
                CP16(sbase + K5_A_OFF(0) + dsto[i], srcA[i]);
                CP16(sbase + K5_B_OFF(0) + dsto[i], srcB[i]);
            }
            CP_COMMIT();

            int buf = 0;
            for (int kt = 0; kt < 24; kt++) {
                if (kt + 1 < 24) {
#pragma unroll
                    for (int i = 0; i < 4; i++) {
                        CP16(sbase + K5_A_OFF(buf^1) + dsto[i], srcA[i] + (kt+1)*32);
                        CP16(sbase + K5_B_OFF(buf^1) + dsto[i], srcB[i] + (kt+1)*32);
                    }
                    CP_COMMIT();
                    asm volatile("cp.async.wait_group 1;" ::: "memory");
                } else {
                    asm volatile("cp.async.wait_group 0;" ::: "memory");
                }
                __syncthreads();

                const float* As = smem + (K5_A_OFF(buf) >> 2);
                const float* Bs = smem + (K5_B_OFF(buf) >> 2);
#pragma unroll
                for (int ks = 0; ks < 4; ks++) {
                    int k0 = ks*8;
                    uint32_t af[4][4], bfr[4][2];
#pragma unroll
                    for (int mi = 0; mi < 4; mi++) {
                        int r0 = warp_m*64 + mi*16 + g;
                        af[mi][0] = __float_as_uint(As[r0*K5_LDA + k0 + tig]);
                        af[mi][1] = __float_as_uint(As[(r0+8)*K5_LDA + k0 + tig]);
                        af[mi][2] = __float_as_uint(As[r0*K5_LDA + k0 + tig + 4]);
                        af[mi][3] = __float_as_uint(As[(r0+8)*K5_LDA + k0 + tig + 4]);
                    }
#pragma unroll
                    for (int ni = 0; ni < 4; ni++) {
                        int c0 = warp_n*32 + ni*8 + g;
                        bfr[ni][0] = __float_as_uint(Bs[c0*K5_LDA + k0 + tig]);
                        bfr[ni][1] = __float_as_uint(Bs[c0*K5_LDA + k0 + tig + 4]);
                    }
#pragma unroll
                    for (int mi = 0; mi < 4; mi++)
#pragma unroll
                        for (int ni = 0; ni < 4; ni++)
                            mma_tf32(cf[mi][ni], af[mi], bfr[ni]);
                }
                __syncthreads();
                buf ^= 1;
            }

            // stage accumulators into smem, then stream to g_logits (coalesced)
#pragma unroll
            for (int mi = 0; mi < 4; mi++) {
                int r0 = warp_m*64 + mi*16 + g;
#pragma unroll
                for (int ni = 0; ni < 4; ni++) {
                    int c0 = warp_n*32 + ni*8 + 2*tig;
                    smem[r0*K5_CS + c0]         = cf[mi][ni][0];
                    smem[r0*K5_CS + c0 + 1]     = cf[mi][ni][1];
                    smem[(r0+8)*K5_CS + c0]     = cf[mi][ni][2];
                    smem[(r0+8)*K5_CS + c0 + 1] = cf[mi][ni][3];
                }
            }
            __syncthreads();
#pragma unroll
            for (int j = 0; j < 16; j++) {
                int idx = tid + j*256;
                int row = idx >> 5, c4 = idx & 31;
                int r = rowBase + row;
                int c = colBase + c4*4;
                const float* Cr = smem + row*K5_CS + c4*4;
                float4 o; o.x = Cr[0]; o.y = Cr[1]; o.z = Cr[2]; o.w = Cr[3];
                *(float4*)(g_logits + (size_t)r*DV + c) = o;
            }
            __syncthreads();
        }
    }

    // ================= full-grid join =================
    gbarX(&g_cntJ, &g_senseJ, (unsigned)G);

    // ================= epilogue (all blocks): out = vis + sigmoid(logit+gsem)*att ==========
    {
        const int total4 = ROWS*DV/4;          // 1,572,864 float4
        for (int i = bid*256 + tid; i < total4; i += G*256) {
            int i4 = i*4;
            int r = i4 / DV;
            int c = i4 - r*DV;
            int b = r >> 10;
            float4 lg = *(const float4*)(g_logits + (size_t)r*DV + c);
            float4 av = *(const float4*)(vis + (size_t)r*DV + c);
            const float* gsp = g_gsem + b*DV;
            const float* at = g_att + b*DV;
            float4 o;
            o.x = av.x + at[c+0] * (1.f/(1.f + __expf(-(lg.x + gsp[c+0]))));
            o.y = av.y + at[c+1] * (1.f/(1.f + __expf(-(lg.y + gsp[c+1]))));
            o.z = av.z + at[c+2] * (1.f/(1.f + __expf(-(lg.z + gsp[c+2]))));
            o.w = av.w + at[c+3] * (1.f/(1.f + __expf(-(lg.w + gsp[c+3]))));
            *(float4*)(out + (size_t)r*DV + c) = o;
        }
    }
}

// ---------------- launcher (single graph node) ----------------
extern "C" void kernel_launch(void* const* d_in, const int* in_sizes, int n_in,
                              void* d_out, int out_size) {
    const float* visual   = (const float*)d_in[0];
    const float* semantic = (const float*)d_in[1];
    const float* Wq = (const float*)d_in[2];
    const float* Wk = (const float*)d_in[3];
    const float* Wv = (const float*)d_in[4];
    const float* Wo = (const float*)d_in[5];
    const float* bo = (const float*)d_in[6];
    const float* Wg = (const float*)d_in[7];
    const float* bg = (const float*)d_in[8];
    const float* gv = (const float*)d_in[9];
    const float* bv = (const float*)d_in[10];
    const float* gs = (const float*)d_in[11];
    const float* bs = (const float*)d_in[12];
    float* out = (float*)d_out;

    cudaFuncSetAttribute(mega, cudaFuncAttributeMaxDynamicSharedMemorySize, MEGA_SMEM);

    int dev = 0;
    cudaGetDevice(&dev);
    int nsm = 148;
    cudaDeviceGetAttribute(&nsm, cudaDevAttrMultiProcessorCount, dev);
    int occ = 0;
    cudaOccupancyMaxActiveBlocksPerMultiprocessor(&occ, mega, 256, MEGA_SMEM);
    if (occ < 1) occ = 1;
    int G = nsm * occ;
    if (G < 2) G = 2;

    mega<<<G, 256, MEGA_SMEM>>>(visual, semantic, Wq, Wk, Wv, Wo, bo,
                                Wg, bg, gv, bv, gs, bs, out);
}